// round 3
// baseline (speedup 1.0000x reference)
#include <cuda_runtime.h>
#include <math.h>

#define FDIM 256
#define BMAX 1024
#define NMAX 1048576
#define WS_STRIDE 132   // floats per k2 row in Ws: 128 data + 4 pad

typedef unsigned long long ull;

// ---------------- scratch (static device globals; no allocation) ----------------
__device__ __align__(128) float g_t1k[BMAX * FDIM];
__device__ __align__(128) float g_t1v[BMAX * FDIM];
__device__ __align__(128) float g_rk [BMAX * FDIM];
__device__ __align__(128) float g_rv [BMAX * FDIM];
__device__ __align__(128) float g_kq [BMAX * FDIM];
__device__ __align__(128) float g_vm [BMAX * FDIM];
__device__ __align__(128) float g_wqT[FDIM * FDIM];
__device__ __align__(128) float g_wc [FDIM * FDIM];   // WcombT[f][k]
__device__ __align__(128) float g_bq [FDIM];
__device__ __align__(128) float g_dot[NMAX];
__device__ __align__(128) float g_smax[BMAX];
__device__ __align__(128) float g_inv [BMAX];

__device__ __forceinline__ float actf(float x) {
    return x / (1.0f + expf(-1.702f * x));
}

__device__ __forceinline__ ull ffma2(ull a, ull b, ull c) {
    ull d;
    asm("fma.rn.f32x2 %0, %1, %2, %3;" : "=l"(d) : "l"(a), "l"(b), "l"(c));
    return d;
}
__device__ __forceinline__ float pairsum(ull v) {
    float2 f = *(float2*)&v;
    return f.x + f.y;
}

// ---------------- transpose 256x256 ----------------
__global__ void transpose256_kernel(const float* __restrict__ in, float* __restrict__ out) {
    __shared__ float tile[32][33];
    int bx = (blockIdx.x & 7) * 32;
    int by = (blockIdx.x >> 3) * 32;
    int tx = threadIdx.x & 31, ty = threadIdx.x >> 5;
    #pragma unroll
    for (int i = 0; i < 32; i += 8)
        tile[ty + i][tx] = in[(size_t)(by + ty + i) * 256 + bx + tx];
    __syncthreads();
    #pragma unroll
    for (int i = 0; i < 32; i += 8)
        out[(size_t)(bx + ty + i) * 256 + by + tx] = tile[tx][ty + i];
}

// ---------------- bq = kbo @ Wq ----------------
__global__ void bq_kernel(const float* __restrict__ kbo, const float* __restrict__ Wq,
                          float* __restrict__ bq) {
    __shared__ float s[256];
    int t = threadIdx.x;
    s[t] = kbo[t];
    __syncthreads();
    float a0 = 0.f, a1 = 0.f, a2 = 0.f, a3 = 0.f;
    #pragma unroll 4
    for (int n = 0; n < 256; n += 4) {
        a0 += s[n + 0] * Wq[(size_t)(n + 0) * 256 + t];
        a1 += s[n + 1] * Wq[(size_t)(n + 1) * 256 + t];
        a2 += s[n + 2] * Wq[(size_t)(n + 2) * 256 + t];
        a3 += s[n + 3] * Wq[(size_t)(n + 3) * 256 + t];
    }
    bq[t] = (a0 + a1) + (a2 + a3);
}

// ---------------- fused layer GEMM (FFMA2) ----------------
// C[m, f0+c] = post( sum_k A[m,k] * Wrow(f0+c, k) + bias )
// flags: 1 = A is rank1 act(E[m]*awf+abf); 2 = residual rank1 (E[m]*rwf+rbf);
//        4 = apply act; 8 = direct W (Wrow(c,k) = W[k][c], W k-major) else W[c][k].
// BM=32, BN=64, 256 threads, FFMA2 packed over k-pairs.
__global__ __launch_bounds__(256)
void layer_kernel(const float* __restrict__ A0, const float* __restrict__ A1,
                  const float* __restrict__ W0, const float* __restrict__ W1,
                  const float* __restrict__ b0, const float* __restrict__ b1,
                  float* __restrict__ C0, float* __restrict__ C1,
                  const float* __restrict__ E,
                  const float* __restrict__ awf0, const float* __restrict__ abf0,
                  const float* __restrict__ awf1, const float* __restrict__ abf1,
                  const float* __restrict__ rwf0, const float* __restrict__ rbf0,
                  const float* __restrict__ rwf1, const float* __restrict__ rbf1,
                  int M, int flags) {
    extern __shared__ float sm[];
    float* As = sm;                 // 32 x 256
    float* Ws = sm + 32 * 256;      // 128 k2-rows x 132

    int br = blockIdx.y;
    const float* A    = br ? A1 : A0;
    const float* W    = br ? W1 : W0;
    const float* bias = br ? b1 : b0;
    const float* awf  = br ? awf1 : awf0;
    const float* abf  = br ? abf1 : abf0;
    const float* rwf  = br ? rwf1 : rwf0;
    const float* rbf  = br ? rbf1 : rbf0;
    float*       C    = br ? C1 : C0;

    int t = threadIdx.x;
    int colTiles = 4;
    int fTile = blockIdx.x & (colTiles - 1);
    int row0  = (blockIdx.x / colTiles) * 32;
    int f0    = fTile * 64;

    // ---- stage A (32 x 256) ----
    if (flags & 1) {
        // rank1: act(E[row]*awf + abf)
        #pragma unroll
        for (int i = 0; i < 8; i++) {
            int idx = i * 256 + t;
            int r   = idx >> 6;
            int c4  = idx & 63;
            float e = (row0 + r < M) ? E[row0 + r] : 0.f;
            float4 w = ((const float4*)awf)[c4];
            float4 bb = abf ? ((const float4*)abf)[c4] : make_float4(0.f, 0.f, 0.f, 0.f);
            float4 v;
            v.x = actf(e * w.x + bb.x);
            v.y = actf(e * w.y + bb.y);
            v.z = actf(e * w.z + bb.z);
            v.w = actf(e * w.w + bb.w);
            *(float4*)(As + r * 256 + c4 * 4) = v;
        }
    } else {
        const float4* A4 = (const float4*)A;
        #pragma unroll
        for (int i = 0; i < 8; i++) {
            int idx = i * 256 + t;
            int r   = idx >> 6;
            int c4  = idx & 63;
            float4 v;
            if (row0 + r < M) v = A4[(size_t)(row0 + r) * 64 + c4];
            else              v = make_float4(0.f, 0.f, 0.f, 0.f);
            *(float4*)(As + r * 256 + c4 * 4) = v;
        }
    }

    // ---- stage W as k-pairs: Ws[k2*132 + c*2 + p] = Wrow(f0+c, 2*k2+p) ----
    if (!(flags & 8)) {
        // transposed layout: Wrow(c,k) = W[f0+c][k]
        int j = t >> 2;          // col 0..63
        int q = t & 3;           // chunk group
        const float4* W4 = (const float4*)W;
        #pragma unroll
        for (int i = 0; i < 16; i++) {
            int c  = q * 16 + i;           // float4 chunk 0..63 (k = 4c)
            float4 v = W4[(size_t)(f0 + j) * 64 + c];
            int k2 = c * 2;
            Ws[k2 * WS_STRIDE + j * 2 + 0]       = v.x;
            Ws[k2 * WS_STRIDE + j * 2 + 1]       = v.y;
            Ws[(k2 + 1) * WS_STRIDE + j * 2 + 0] = v.z;
            Ws[(k2 + 1) * WS_STRIDE + j * 2 + 1] = v.w;
        }
    } else {
        // direct layout: Wrow(c,k) = W[k][f0+c]  (W is FDIM x FDIM row-major, row = k)
        int q = t & 15;          // col quad within tile
        int n = t >> 4;          // 0..15
        const float4* W4 = (const float4*)W;
        #pragma unroll
        for (int i = 0; i < 16; i++) {
            int k = i * 16 + n;
            float4 v = W4[(size_t)k * 64 + (f0 >> 2) + q];
            int k2 = k >> 1, p = k & 1;
            Ws[k2 * WS_STRIDE + (q * 4 + 0) * 2 + p] = v.x;
            Ws[k2 * WS_STRIDE + (q * 4 + 1) * 2 + p] = v.y;
            Ws[k2 * WS_STRIDE + (q * 4 + 2) * 2 + p] = v.z;
            Ws[k2 * WS_STRIDE + (q * 4 + 3) * 2 + p] = v.w;
        }
    }
    __syncthreads();

    // ---- compute: 2 rows x 4 cols per thread ----
    int f4 = t & 15;             // col group: cols f0 + f4*4 .. +3
    int rw = t >> 4;             // row pair: rows rw*2, rw*2+1
    const float* as0 = As + (rw * 2) * 256;
    const float* as1 = as0 + 256;

    ull acc00 = 0, acc01 = 0, acc02 = 0, acc03 = 0;
    ull acc10 = 0, acc11 = 0, acc12 = 0, acc13 = 0;

    #pragma unroll 4
    for (int k2 = 0; k2 < 128; k2++) {
        const float* wrow = Ws + k2 * WS_STRIDE + f4 * 8;
        ulonglong2 wA = *(const ulonglong2*)(wrow);
        ulonglong2 wB = *(const ulonglong2*)(wrow + 4);
        ull a0 = *(const ull*)(as0 + 2 * k2);
        ull a1 = *(const ull*)(as1 + 2 * k2);
        acc00 = ffma2(a0, wA.x, acc00);
        acc01 = ffma2(a0, wA.y, acc01);
        acc02 = ffma2(a0, wB.x, acc02);
        acc03 = ffma2(a0, wB.y, acc03);
        acc10 = ffma2(a1, wA.x, acc10);
        acc11 = ffma2(a1, wA.y, acc11);
        acc12 = ffma2(a1, wB.x, acc12);
        acc13 = ffma2(a1, wB.y, acc13);
    }

    // ---- epilogue ----
    int cbase = f0 + f4 * 4;
    float4 bb = bias ? *(const float4*)(bias + cbase) : make_float4(0.f, 0.f, 0.f, 0.f);

    float4 o0 = make_float4(pairsum(acc00) + bb.x, pairsum(acc01) + bb.y,
                            pairsum(acc02) + bb.z, pairsum(acc03) + bb.w);
    float4 o1 = make_float4(pairsum(acc10) + bb.x, pairsum(acc11) + bb.y,
                            pairsum(acc12) + bb.z, pairsum(acc13) + bb.w);

    float4 rw4 = make_float4(0.f, 0.f, 0.f, 0.f), rb4 = make_float4(0.f, 0.f, 0.f, 0.f);
    if (flags & 2) {
        rw4 = *(const float4*)(rwf + cbase);
        if (rbf) rb4 = *(const float4*)(rbf + cbase);
    }

    #pragma unroll
    for (int rr = 0; rr < 2; rr++) {
        int row = row0 + rw * 2 + rr;
        if (row >= M) continue;
        float4 v = rr ? o1 : o0;
        if (flags & 2) {
            float e = E[row];
            v.x += e * rw4.x + rb4.x;
            v.y += e * rw4.y + rb4.y;
            v.z += e * rw4.z + rb4.z;
            v.w += e * rw4.w + rb4.w;
        }
        if (flags & 4) {
            v.x = actf(v.x); v.y = actf(v.y); v.z = actf(v.z); v.w = actf(v.w);
        }
        *(float4*)(C + (size_t)row * 256 + cbase) = v;
    }
}

// ---------------- seg helpers (int32 buffer that may really be int64) ----------------
__device__ __forceinline__ int seg_is64(const int* __restrict__ s, int N) {
    // sorted, max = B-1 > 0. int64 LE => int32 view at N-1 is a high word = 0.
    return s[N - 1] == 0;
}

// ---------------- dot pass: dot[i] = x[i,:] . kq[seg[i],:] ----------------
__global__ void dot_kernel(const float4* __restrict__ x,
                           const int* __restrict__ seg32,
                           const float* __restrict__ kq,
                           float* __restrict__ dotv,
                           int N) {
    int gw   = (blockIdx.x * blockDim.x + threadIdx.x) >> 5;
    int lane = threadIdx.x & 31;
    if (gw >= N) return;
    int is64 = seg_is64(seg32, N);
    int b = seg32[is64 ? 2 * gw : gw];
    const float4* xr = x + (size_t)gw * 64;
    const float4* kr = (const float4*)kq + (size_t)b * 64;

    float4 a0 = xr[lane];
    float4 k0 = kr[lane];
    float4 a1 = xr[lane + 32];
    float4 k1 = kr[lane + 32];
    float s = a0.x * k0.x + a0.y * k0.y + a0.z * k0.z + a0.w * k0.w
            + a1.x * k1.x + a1.y * k1.y + a1.z * k1.z + a1.w * k1.w;
    #pragma unroll
    for (int o = 16; o; o >>= 1) s += __shfl_xor_sync(0xffffffffu, s, o);
    if (lane == 0) dotv[gw] = s;
}

// ---------------- segment reduce (deterministic, per-segment block) ----------------
__device__ __forceinline__ int lowerb(const int* __restrict__ s, int n, int v, int st) {
    int lo = 0, hi = n;
    while (lo < hi) {
        int mid = (lo + hi) >> 1;
        if (s[mid * st] < v) lo = mid + 1; else hi = mid;
    }
    return lo;
}

__global__ void segreduce_kernel(const int* __restrict__ seg32,
                                 const float* __restrict__ dotv,
                                 float* __restrict__ smax,
                                 float* __restrict__ invnorm,
                                 int N, float scale) {
    __shared__ float red[256];
    __shared__ int sse[2];
    int b = blockIdx.x;
    int t = threadIdx.x;
    if (t == 0) {
        int st = seg_is64(seg32, N) ? 2 : 1;
        sse[0] = lowerb(seg32, N, b, st);
        sse[1] = lowerb(seg32, N, b + 1, st);
    }
    __syncthreads();
    int start = sse[0], end = sse[1];

    float m = -3.4e38f;
    for (int i = start + t; i < end; i += 256) m = fmaxf(m, dotv[i]);
    red[t] = m;
    __syncthreads();
    #pragma unroll
    for (int s = 128; s; s >>= 1) {
        if (t < s) red[t] = fmaxf(red[t], red[t + s]);
        __syncthreads();
    }
    float mx = red[0];
    __syncthreads();

    float ss = 0.f;
    for (int i = start + t; i < end; i += 256) ss += expf((dotv[i] - mx) * scale);
    red[t] = ss;
    __syncthreads();
    #pragma unroll
    for (int s = 128; s; s >>= 1) {
        if (t < s) red[t] += red[t + s];
        __syncthreads();
    }
    if (t == 0) {
        smax[b] = mx;
        invnorm[b] = 1.f / (red[0] + 1e-8f);
    }
}

// ---------------- output pass ----------------
__global__ void out_kernel(const float* __restrict__ dotv,
                           const int* __restrict__ seg32,
                           const float* __restrict__ vm,
                           const float* __restrict__ smax,
                           const float* __restrict__ invnorm,
                           float4* __restrict__ out,
                           int N, float scale) {
    int gw   = (blockIdx.x * blockDim.x + threadIdx.x) >> 5;
    int lane = threadIdx.x & 31;
    if (gw >= N) return;
    int is64 = seg_is64(seg32, N);
    int b = seg32[is64 ? 2 * gw : gw];
    float coef = expf((dotv[gw] - smax[b]) * scale) * invnorm[b];
    const float4* vr = (const float4*)vm + (size_t)b * 64;
    float4* orow = out + (size_t)gw * 64;

    float4 v0 = vr[lane];
    v0.x *= coef; v0.y *= coef; v0.z *= coef; v0.w *= coef;
    orow[lane] = v0;
    float4 v1 = vr[lane + 32];
    v1.x *= coef; v1.y *= coef; v1.z *= coef; v1.w *= coef;
    orow[lane + 32] = v1;
}

// ---------------- launcher ----------------
extern "C" void kernel_launch(void* const* d_in, const int* in_sizes, int n_in,
                              void* d_out, int out_size) {
    int sh = (n_in >= 17) ? 0 : 1;
    const float* x    = (const float*)d_in[0];
    const float* E    = (const float*)d_in[1];
    const int*   seg  = (const int*)  d_in[3 - sh];
    const float* Wq   = (const float*)d_in[4 - sh];
    const float* Wkf  = (const float*)d_in[5 - sh];
    const float* bkf  = (const float*)d_in[6 - sh];
    const float* Wvf  = (const float*)d_in[7 - sh];
    const float* kW1  = (const float*)d_in[8 - sh];
    const float* kb1  = (const float*)d_in[9 - sh];
    const float* kW2  = (const float*)d_in[10 - sh];
    const float* kb2  = (const float*)d_in[11 - sh];
    const float* kWo  = (const float*)d_in[12 - sh];
    const float* kbo  = (const float*)d_in[13 - sh];
    const float* vW1  = (const float*)d_in[14 - sh];
    const float* vW2  = (const float*)d_in[15 - sh];
    const float* vWo  = (const float*)d_in[16 - sh];

    int B = in_sizes[1];
    int N = in_sizes[3 - sh];
    float scale = 1.f / 16.f;   // 1/sqrt(256)

    float *t1k, *t1v, *rk, *rv, *kq, *vm, *wqT, *wc, *bq, *dotv, *smax, *inv;
    cudaGetSymbolAddress((void**)&t1k, g_t1k);
    cudaGetSymbolAddress((void**)&t1v, g_t1v);
    cudaGetSymbolAddress((void**)&rk,  g_rk);
    cudaGetSymbolAddress((void**)&rv,  g_rv);
    cudaGetSymbolAddress((void**)&kq,  g_kq);
    cudaGetSymbolAddress((void**)&vm,  g_vm);
    cudaGetSymbolAddress((void**)&wqT, g_wqT);
    cudaGetSymbolAddress((void**)&wc,  g_wc);
    cudaGetSymbolAddress((void**)&bq,  g_bq);
    cudaGetSymbolAddress((void**)&dotv, g_dot);
    cudaGetSymbolAddress((void**)&smax, g_smax);
    cudaGetSymbolAddress((void**)&inv,  g_inv);

    const int SMEM = (32 * 256 + 128 * WS_STRIDE) * (int)sizeof(float);  // 100352 B
    static int smemSet = 0;
    cudaFuncSetAttribute(layer_kernel, cudaFuncAttributeMaxDynamicSharedMemorySize, SMEM);
    (void)smemSet;

    // --- prologue (independent of E/x chain) ---
    transpose256_kernel<<<64, 256>>>(Wq, wqT);
    bq_kernel<<<1, 256>>>(kbo, Wq, bq);
    // WcombT = WqT @ kWo (direct-W mode): WcombT[f][k] = sum_n Wq[n][f]*kWo[n][k]
    {
        dim3 grid(8 * 4, 1);
        layer_kernel<<<grid, 256, SMEM>>>(wqT, wqT, kWo, kWo, nullptr, nullptr,
                                          wc, wc, nullptr,
                                          nullptr, nullptr, nullptr, nullptr,
                                          nullptr, nullptr, nullptr, nullptr,
                                          256, /*flags=*/8);
    }

    // --- resMLP chain (k and v branches via gridDim.y) ---
    int rowTiles = (B + 31) / 32;
    dim3 lgrid(rowTiles * 4, 2);
    // L1: t1 = act( act(rank1(E)) @ W1^T + b1 )
    layer_kernel<<<lgrid, 256, SMEM>>>(nullptr, nullptr, kW1, vW1, kb1, nullptr,
                                       t1k, t1v, E,
                                       Wkf, bkf, Wvf, nullptr,
                                       nullptr, nullptr, nullptr, nullptr,
                                       B, /*flags=*/1 | 4);
    // L2: r = act( rank1(E) + t1 @ W2^T + b2 )
    layer_kernel<<<lgrid, 256, SMEM>>>(t1k, t1v, kW2, vW2, kb2, nullptr,
                                       rk, rv, E,
                                       nullptr, nullptr, nullptr, nullptr,
                                       Wkf, bkf, Wvf, nullptr,
                                       B, /*flags=*/2 | 4);
    // L3: kq = rk @ WcombT^T + bq ; vm = rv @ vWo^T
    layer_kernel<<<lgrid, 256, SMEM>>>(rk, rv, wc, vWo, bq, nullptr,
                                       kq, vm, nullptr,
                                       nullptr, nullptr, nullptr, nullptr,
                                       nullptr, nullptr, nullptr, nullptr,
                                       B, /*flags=*/0);

    // --- streaming passes ---
    int nwb = (N * 32 + 255) / 256;
    dot_kernel<<<nwb, 256>>>((const float4*)x, seg, kq, dotv, N);
    segreduce_kernel<<<B, 256>>>(seg, dotv, smax, inv, N, scale);
    out_kernel<<<nwb, 256>>>(dotv, seg, vm, smax, inv, (float4*)d_out, N, scale);
}